// round 1
// baseline (speedup 1.0000x reference)
#include <cuda_runtime.h>

#define VOX 262144   // 16 * 128 * 128
#define EPSV 1e-5f

// ---------------- scratch (device globals; no allocation allowed) ----------
__device__ int   g_count;
__device__ int   g_map[VOX];
__device__ int   g_list[VOX];
__device__ float g_xa[VOX * 64];      // compact input  [slot][64]
__device__ float g_s1[VOX * 64];      // branch1 intermediate
__device__ float g_r1[VOX * 64];      // branch2 intermediate
__device__ float g_sc[VOX * 128];     // shortcut       [slot][128]
__device__ float g_Wt1a[9 * 64 * 64];
__device__ float g_Wt1b[9 * 64 * 128];
__device__ float g_Wt2a[9 * 64 * 64];
__device__ float g_Wt2b[9 * 64 * 128];

// ---------------- tiny helpers --------------------------------------------
__global__ void reset_k() { g_count = 0; }

// W is OIDHW flattened: idx = (o*64 + i)*9 + t  ->  Wt[(t*64 + i)*CO + o]
__global__ void transpose_w(const float* __restrict__ W, float* __restrict__ Wt, int CO) {
    int idx = blockIdx.x * 256 + threadIdx.x;
    if (idx >= CO * 64 * 9) return;
    int t  = idx % 9;
    int oi = idx / 9;
    int i  = oi & 63;
    int o  = oi >> 6;
    Wt[(t * 64 + i) * CO + o] = W[idx];
}

// ---------------- pass 0: activity detection + compaction ------------------
__global__ void __launch_bounds__(256) pass0(const float* __restrict__ x) {
    int v = blockIdx.x * 256 + threadIdx.x;
    float vals[64];
    bool active = false;
#pragma unroll
    for (int c = 0; c < 64; c++) {
        vals[c] = x[c * VOX + v];
        active |= (vals[c] != 0.0f);
    }
    unsigned m   = __ballot_sync(0xffffffffu, active);
    int lane     = threadIdx.x & 31;
    int slot     = -1;
    if (m) {
        int leader = __ffs(m) - 1;
        int base   = 0;
        if (lane == leader) base = atomicAdd(&g_count, __popc(m));
        base = __shfl_sync(0xffffffffu, base, leader);
        if (active) slot = base + __popc(m & ((1u << lane) - 1u));
    }
    g_map[v] = slot;
    if (active) {
        g_list[slot] = v;
#pragma unroll
        for (int c = 0; c < 64; c += 4)
            *(float4*)&g_xa[slot * 64 + c] =
                make_float4(vals[c], vals[c + 1], vals[c + 2], vals[c + 3]);
    }
}

// ---------------- gather-GEMM conv + fused GroupNorm (+LeakyReLU) ----------
// CTYPE 0: (3,3,1) taps -> (dd,dh,0);  1: (1,3,3) -> (0,dh,dw);  2: (3,1,3) -> (dd,0,dw)
// Block: 64 voxels x COUT outputs, 256 threads.
template <int COUT, int CTYPE, bool LRELU, bool FINAL>
__global__ void __launch_bounds__(256) conv_gn(
    const float* __restrict__ in, const float* __restrict__ Wt,
    const float* __restrict__ gamma, const float* __restrict__ beta,
    float* __restrict__ outc, const float* __restrict__ shortcut,
    float* __restrict__ outd)
{
    const int N    = g_count;
    const int base = blockIdx.x * 64;
    if (base >= N) return;

    constexpr int TX = COUT / 4;         // threads along out-channels (x4 each)
    constexpr int VT = 64 * TX / 256;    // voxels per thread

    extern __shared__ float sbuf[];
    float* Xs = sbuf;                    // [64][68]
    float* Ws = sbuf + 64 * 68;          // [64][COUT]
    __shared__ int nsrow[64];

    const int t  = threadIdx.x;
    const int tx = t % TX;
    const int ty = t / TX;

    float acc[VT][4];
#pragma unroll
    for (int j = 0; j < VT; j++) acc[j][0] = acc[j][1] = acc[j][2] = acc[j][3] = 0.f;

    for (int tap = 0; tap < 9; tap++) {
        // stage this tap's 64xCOUT weight tile
        const float4* wsrc = (const float4*)(Wt + tap * 64 * COUT);
#pragma unroll
        for (int k = t; k < 16 * COUT; k += 256)
            ((float4*)Ws)[k] = wsrc[k];

        // neighbor slot per row
        if (t < 64) {
            int slot = base + t, ns = -1;
            if (slot < N) {
                int v = g_list[slot];
                int d = v >> 14, h = (v >> 7) & 127, w = v & 127;
                int dd, dh, dw;
                if (CTYPE == 0)      { dd = tap / 3 - 1; dh = tap % 3 - 1; dw = 0; }
                else if (CTYPE == 1) { dd = 0;           dh = tap / 3 - 1; dw = tap % 3 - 1; }
                else                 { dd = tap / 3 - 1; dh = 0;           dw = tap % 3 - 1; }
                d += dd; h += dh; w += dw;
                if ((unsigned)d < 16u && (unsigned)h < 128u && (unsigned)w < 128u)
                    ns = g_map[(d << 14) | (h << 7) | w];
            }
            nsrow[t] = ns;
        }
        __syncthreads();

        // gather 64 input rows (256B each, contiguous) into Xs
        {
            int r = t >> 2, p = t & 3;
            int ns = nsrow[r];
            const float4* src = (const float4*)(in + ns * 64 + p * 16);
#pragma unroll
            for (int k = 0; k < 4; k++) {
                float4 val = (ns >= 0) ? src[k] : make_float4(0.f, 0.f, 0.f, 0.f);
                *(float4*)&Xs[r * 68 + p * 16 + k * 4] = val;
            }
        }
        __syncthreads();

        // microkernel: vectorized a-loads over cin, b float4 over cout
#pragma unroll 2
        for (int i0 = 0; i0 < 64; i0 += 4) {
            float4 a4[VT];
#pragma unroll
            for (int j = 0; j < VT; j++)
                a4[j] = *(const float4*)&Xs[(ty * VT + j) * 68 + i0];
#pragma unroll
            for (int ii = 0; ii < 4; ii++) {
                float4 b = *(const float4*)&Ws[(i0 + ii) * COUT + tx * 4];
#pragma unroll
                for (int j = 0; j < VT; j++) {
                    float a = (ii == 0) ? a4[j].x : (ii == 1) ? a4[j].y
                            : (ii == 2) ? a4[j].z : a4[j].w;
                    acc[j][0] = fmaf(a, b.x, acc[j][0]);
                    acc[j][1] = fmaf(a, b.y, acc[j][1]);
                    acc[j][2] = fmaf(a, b.z, acc[j][2]);
                    acc[j][3] = fmaf(a, b.w, acc[j][3]);
                }
            }
        }
        __syncthreads();
    }

    // spill conv results to smem for the GroupNorm remap
    float* S = sbuf;  // [64][COUT], reuses Xs+Ws region
#pragma unroll
    for (int j = 0; j < VT; j++)
        *(float4*)&S[(ty * VT + j) * COUT + tx * 4] =
            make_float4(acc[j][0], acc[j][1], acc[j][2], acc[j][3]);
    __syncthreads();

    // GroupNorm: 32 groups of CG consecutive channels, per-voxel stats
    constexpr int CG = COUT / 32;
    for (int task = t; task < 64 * 32; task += 256) {
        int vox  = task >> 5;
        int g    = task & 31;
        int slot = base + vox;
        if (slot >= N) continue;
        float vals[CG], sum = 0.f;
#pragma unroll
        for (int c = 0; c < CG; c++) { vals[c] = S[vox * COUT + g * CG + c]; sum += vals[c]; }
        float mu  = sum * (1.0f / CG);
        float var = 0.f;
#pragma unroll
        for (int c = 0; c < CG; c++) { float d = vals[c] - mu; var += d * d; }
        var *= (1.0f / CG);
        float rs = rsqrtf(var + EPSV);
        if (!FINAL) {
#pragma unroll
            for (int c = 0; c < CG; c++) {
                int cc  = g * CG + c;
                float o = (vals[c] - mu) * rs * gamma[cc] + beta[cc];
                if (LRELU) o = (o > 0.f) ? o : 0.01f * o;
                outc[slot * COUT + cc] = o;
            }
        } else {
            int v = g_list[slot];
#pragma unroll
            for (int c = 0; c < CG; c++) {
                int cc  = g * CG + c;
                float o = (vals[c] - mu) * rs * gamma[cc] + beta[cc]
                        + shortcut[slot * 128 + cc];
                outd[cc * VOX + v] = o;
            }
        }
    }
}

// ---------------- launch ----------------------------------------------------
extern "C" void kernel_launch(void* const* d_in, const int* in_sizes, int n_in,
                              void* d_out, int out_size) {
    (void)in_sizes; (void)n_in; (void)out_size;
    const float* x   = (const float*)d_in[0];
    // d_in[1] = mask (dtype uncertain) — activity derived from x instead.
    const float* W1a = (const float*)d_in[2];
    const float* g1a = (const float*)d_in[3];
    const float* b1a = (const float*)d_in[4];
    const float* W1b = (const float*)d_in[5];
    const float* g1b = (const float*)d_in[6];
    const float* b1b = (const float*)d_in[7];
    const float* W2a = (const float*)d_in[8];
    const float* g2a = (const float*)d_in[9];
    const float* b2a = (const float*)d_in[10];
    const float* W2b = (const float*)d_in[11];
    const float* g2b = (const float*)d_in[12];
    const float* b2b = (const float*)d_in[13];
    float* out = (float*)d_out;

    float *p_xa, *p_s1, *p_r1, *p_sc, *p_w1a, *p_w1b, *p_w2a, *p_w2b;
    cudaGetSymbolAddress((void**)&p_xa,  g_xa);
    cudaGetSymbolAddress((void**)&p_s1,  g_s1);
    cudaGetSymbolAddress((void**)&p_r1,  g_r1);
    cudaGetSymbolAddress((void**)&p_sc,  g_sc);
    cudaGetSymbolAddress((void**)&p_w1a, g_Wt1a);
    cudaGetSymbolAddress((void**)&p_w1b, g_Wt1b);
    cudaGetSymbolAddress((void**)&p_w2a, g_Wt2a);
    cudaGetSymbolAddress((void**)&p_w2b, g_Wt2b);

    const int SM64  = (64 * 68 + 64 * 64) * 4;   // 33792 B
    const int SM128 = (64 * 68 + 64 * 128) * 4;  // 50176 B
    cudaFuncSetAttribute(conv_gn<128, 1, false, false>,
                         cudaFuncAttributeMaxDynamicSharedMemorySize, SM128);
    cudaFuncSetAttribute(conv_gn<128, 0, false, true>,
                         cudaFuncAttributeMaxDynamicSharedMemorySize, SM128);

    cudaMemsetAsync(out, 0, (size_t)VOX * 128 * sizeof(float), 0);
    reset_k<<<1, 1>>>();
    transpose_w<<<(64 * 64 * 9 + 255) / 256, 256>>>(W1a, p_w1a, 64);
    transpose_w<<<(128 * 64 * 9 + 255) / 256, 256>>>(W1b, p_w1b, 128);
    transpose_w<<<(64 * 64 * 9 + 255) / 256, 256>>>(W2a, p_w2a, 64);
    transpose_w<<<(128 * 64 * 9 + 255) / 256, 256>>>(W2b, p_w2b, 128);
    pass0<<<VOX / 256, 256>>>(x);

    const int NB = VOX / 64;  // worst-case all-active; blocks early-exit past g_count
    conv_gn<64, 0, true,  false><<<NB, 256, SM64>>>(p_xa, p_w1a, g1a, b1a, p_s1, nullptr, nullptr);
    conv_gn<128, 1, false, false><<<NB, 256, SM128>>>(p_s1, p_w1b, g1b, b1b, p_sc, nullptr, nullptr);
    conv_gn<64, 2, true,  false><<<NB, 256, SM64>>>(p_xa, p_w2a, g2a, b2a, p_r1, nullptr, nullptr);
    conv_gn<128, 0, false, true><<<NB, 256, SM128>>>(p_r1, p_w2b, g2b, b2b, nullptr, p_sc, out);
}

// round 4
// speedup vs baseline: 1.0660x; 1.0660x over previous
#include <cuda_runtime.h>

#define VOX 262144   // 16 * 128 * 128
#define EPSV 1e-5f

// ---------------- scratch (device globals; no allocation allowed) ----------
__device__ int   g_count;
__device__ int   g_map[VOX];
__device__ int   g_list[VOX];
__device__ float g_xa[VOX * 64];      // compact input  [slot][64]
__device__ float g_s1[VOX * 64];      // branch1 intermediate
__device__ float g_r1[VOX * 64];      // branch2 intermediate
__device__ float g_sc[VOX * 128];     // shortcut       [slot][128]
__device__ float g_Wt1a[9 * 64 * 64];
__device__ float g_Wt1b[9 * 64 * 128];
__device__ float g_Wt2a[9 * 64 * 64];
__device__ float g_Wt2b[9 * 64 * 128];

// ---------------- packed fp32 helpers (sm_103a f32x2) ----------------------
__device__ __forceinline__ void ffma2(unsigned long long& d,
                                      unsigned long long a,
                                      unsigned long long b) {
    asm("fma.rn.f32x2 %0, %1, %2, %0;" : "+l"(d) : "l"(a), "l"(b));
}
__device__ __forceinline__ unsigned long long pack2(float x) {
    unsigned long long r;
    asm("mov.b64 %0, {%1, %1};" : "=l"(r) : "f"(x));
    return r;
}

// ---------------- prep: reset counter + transpose all 4 weights -------------
// W is OIDHW flattened: idx = (o*64 + i)*9 + t  ->  Wt[(t*64 + i)*CO + o]
__device__ __forceinline__ void tr_one(const float* __restrict__ W,
                                       float* __restrict__ Wt, int CO, int idx) {
    int t  = idx % 9;
    int oi = idx / 9;
    int i  = oi & 63;
    int o  = oi / 64;
    Wt[(t * 64 + i) * CO + o] = W[idx];
}

__global__ void __launch_bounds__(256) prep(
    const float* __restrict__ W1a, const float* __restrict__ W1b,
    const float* __restrict__ W2a, const float* __restrict__ W2b)
{
    int idx = blockIdx.x * 256 + threadIdx.x;
    if (idx == 0) g_count = 0;
    const int N64 = 64 * 64 * 9, N128 = 128 * 64 * 9;
    if (idx < N64)                      tr_one(W1a, g_Wt1a, 64,  idx);
    else if ((idx -= N64)  < N128)      tr_one(W1b, g_Wt1b, 128, idx);
    else if ((idx -= N128) < N64)       tr_one(W2a, g_Wt2a, 64,  idx);
    else if ((idx -= N64)  < N128)      tr_one(W2b, g_Wt2b, 128, idx);
}

// ---------------- pass 0: activity detection + compaction ------------------
__global__ void __launch_bounds__(256) pass0(const float* __restrict__ x) {
    int v = blockIdx.x * 256 + threadIdx.x;
    float vals[64];
    bool active = false;
#pragma unroll
    for (int c = 0; c < 64; c++) {
        vals[c] = x[c * VOX + v];
        active |= (vals[c] != 0.0f);
    }
    unsigned m   = __ballot_sync(0xffffffffu, active);
    int lane     = threadIdx.x & 31;
    int slot     = -1;
    if (m) {
        int leader = __ffs(m) - 1;
        int base   = 0;
        if (lane == leader) base = atomicAdd(&g_count, __popc(m));
        base = __shfl_sync(0xffffffffu, base, leader);
        if (active) slot = base + __popc(m & ((1u << lane) - 1u));
    }
    g_map[v] = slot;
    if (active) {
        g_list[slot] = v;
#pragma unroll
        for (int c = 0; c < 64; c += 4)
            *(float4*)&g_xa[slot * 64 + c] =
                make_float4(vals[c], vals[c + 1], vals[c + 2], vals[c + 3]);
    }
}

// ---------------- gather-GEMM conv + fused GroupNorm (+LeakyReLU) ----------
// CTYPE 0: (3,3,1) taps -> (dd,dh,0);  1: (1,3,3) -> (0,dh,dw);  2: (3,1,3) -> (dd,0,dw)
// Block: 64 voxels x COUT outputs, 256 threads. f32x2 packed mainloop.
template <int COUT, int CTYPE, bool LRELU, bool FINAL>
__global__ void __launch_bounds__(256) conv_gn(
    const float* __restrict__ in, const float* __restrict__ Wt,
    const float* __restrict__ gamma, const float* __restrict__ beta,
    float* __restrict__ outc, const float* __restrict__ shortcut,
    float* __restrict__ outd)
{
    const int N    = g_count;
    const int base = blockIdx.x * 64;
    if (base >= N) return;

    constexpr int TX = COUT / 4;         // threads along out-channels (x4 each)
    constexpr int VT = 64 * TX / 256;    // voxels per thread

    extern __shared__ float sbuf[];
    float* Xs = sbuf;                    // [64][68]
    float* Ws = sbuf + 64 * 68;          // [64][COUT]
    __shared__ int nsrow[64];

    const int t  = threadIdx.x;
    const int tx = t % TX;
    const int ty = t / TX;

    // acc[j][0] = (cout0,cout1), acc[j][1] = (cout2,cout3) packed fp32 pairs
    unsigned long long acc[VT][2];
#pragma unroll
    for (int j = 0; j < VT; j++) { acc[j][0] = 0ull; acc[j][1] = 0ull; }

    for (int tap = 0; tap < 9; tap++) {
        // stage this tap's 64xCOUT weight tile
        const float4* wsrc = (const float4*)(Wt + tap * 64 * COUT);
#pragma unroll
        for (int k = t; k < 16 * COUT; k += 256)
            ((float4*)Ws)[k] = wsrc[k];

        // neighbor slot per row
        if (t < 64) {
            int slot = base + t, ns = -1;
            if (slot < N) {
                int v = g_list[slot];
                int d = v >> 14, h = (v >> 7) & 127, w = v & 127;
                int dd, dh, dw;
                if (CTYPE == 0)      { dd = tap / 3 - 1; dh = tap % 3 - 1; dw = 0; }
                else if (CTYPE == 1) { dd = 0;           dh = tap / 3 - 1; dw = tap % 3 - 1; }
                else                 { dd = tap / 3 - 1; dh = 0;           dw = tap % 3 - 1; }
                d += dd; h += dh; w += dw;
                if ((unsigned)d < 16u && (unsigned)h < 128u && (unsigned)w < 128u)
                    ns = g_map[(d << 14) | (h << 7) | w];
            }
            nsrow[t] = ns;
        }
        __syncthreads();

        // gather 64 input rows (256B each, contiguous) into Xs
        {
            int r = t >> 2, p = t & 3;
            int ns = nsrow[r];
            const float4* src = (const float4*)(in + ns * 64 + p * 16);
#pragma unroll
            for (int k = 0; k < 4; k++) {
                float4 val = (ns >= 0) ? src[k] : make_float4(0.f, 0.f, 0.f, 0.f);
                *(float4*)&Xs[r * 68 + p * 16 + k * 4] = val;
            }
        }
        __syncthreads();

        // packed microkernel: broadcast a over cin, f32x2 pairs over cout
#pragma unroll 2
        for (int i0 = 0; i0 < 64; i0 += 4) {
            float4 a4[VT];
#pragma unroll
            for (int j = 0; j < VT; j++)
                a4[j] = *(const float4*)&Xs[(ty * VT + j) * 68 + i0];
#pragma unroll
            for (int ii = 0; ii < 4; ii++) {
                ulonglong2 b = *(const ulonglong2*)&Ws[(i0 + ii) * COUT + tx * 4];
#pragma unroll
                for (int j = 0; j < VT; j++) {
                    float a = (ii == 0) ? a4[j].x : (ii == 1) ? a4[j].y
                            : (ii == 2) ? a4[j].z : a4[j].w;
                    unsigned long long aa = pack2(a);
                    ffma2(acc[j][0], aa, b.x);
                    ffma2(acc[j][1], aa, b.y);
                }
            }
        }
        __syncthreads();
    }

    // spill conv results to smem for the GroupNorm remap
    float* S = sbuf;  // [64][COUT], reuses Xs+Ws region
#pragma unroll
    for (int j = 0; j < VT; j++) {
        float2 lo = *(float2*)&acc[j][0];
        float2 hi = *(float2*)&acc[j][1];
        *(float4*)&S[(ty * VT + j) * COUT + tx * 4] =
            make_float4(lo.x, lo.y, hi.x, hi.y);
    }
    __syncthreads();

    // GroupNorm: 32 groups of CG consecutive channels, per-voxel stats
    constexpr int CG = COUT / 32;
    for (int task = t; task < 64 * 32; task += 256) {
        int vox  = task >> 5;
        int g    = task & 31;
        int slot = base + vox;
        if (slot >= N) continue;
        float vals[CG], sum = 0.f;
#pragma unroll
        for (int c = 0; c < CG; c++) { vals[c] = S[vox * COUT + g * CG + c]; sum += vals[c]; }
        float mu  = sum * (1.0f / CG);
        float var = 0.f;
#pragma unroll
        for (int c = 0; c < CG; c++) { float d = vals[c] - mu; var += d * d; }
        var *= (1.0f / CG);
        float rs = rsqrtf(var + EPSV);
        if (!FINAL) {
#pragma unroll
            for (int c = 0; c < CG; c++) {
                int cc  = g * CG + c;
                float o = (vals[c] - mu) * rs * gamma[cc] + beta[cc];
                if (LRELU) o = (o > 0.f) ? o : 0.01f * o;
                outc[slot * COUT + cc] = o;
            }
        } else {
            int v = g_list[slot];
#pragma unroll
            for (int c = 0; c < CG; c++) {
                int cc  = g * CG + c;
                float o = (vals[c] - mu) * rs * gamma[cc] + beta[cc]
                        + shortcut[slot * 128 + cc];
                outd[cc * VOX + v] = o;
            }
        }
    }
}

// ---------------- launch ----------------------------------------------------
extern "C" void kernel_launch(void* const* d_in, const int* in_sizes, int n_in,
                              void* d_out, int out_size) {
    (void)in_sizes; (void)n_in; (void)out_size;
    const float* x   = (const float*)d_in[0];
    // d_in[1] = mask (dtype uncertain) — activity derived from x instead.
    const float* W1a = (const float*)d_in[2];
    const float* g1a = (const float*)d_in[3];
    const float* b1a = (const float*)d_in[4];
    const float* W1b = (const float*)d_in[5];
    const float* g1b = (const float*)d_in[6];
    const float* b1b = (const float*)d_in[7];
    const float* W2a = (const float*)d_in[8];
    const float* g2a = (const float*)d_in[9];
    const float* b2a = (const float*)d_in[10];
    const float* W2b = (const float*)d_in[11];
    const float* g2b = (const float*)d_in[12];
    const float* b2b = (const float*)d_in[13];
    float* out = (float*)d_out;

    float *p_xa, *p_s1, *p_r1, *p_sc, *p_w1a, *p_w1b, *p_w2a, *p_w2b;
    cudaGetSymbolAddress((void**)&p_xa,  g_xa);
    cudaGetSymbolAddress((void**)&p_s1,  g_s1);
    cudaGetSymbolAddress((void**)&p_r1,  g_r1);
    cudaGetSymbolAddress((void**)&p_sc,  g_sc);
    cudaGetSymbolAddress((void**)&p_w1a, g_Wt1a);
    cudaGetSymbolAddress((void**)&p_w1b, g_Wt1b);
    cudaGetSymbolAddress((void**)&p_w2a, g_Wt2a);
    cudaGetSymbolAddress((void**)&p_w2b, g_Wt2b);

    const int SM64  = (64 * 68 + 64 * 64) * 4;   // 33792 B
    const int SM128 = (64 * 68 + 64 * 128) * 4;  // 50176 B
    cudaFuncSetAttribute(conv_gn<128, 1, false, false>,
                         cudaFuncAttributeMaxDynamicSharedMemorySize, SM128);
    cudaFuncSetAttribute(conv_gn<128, 0, false, true>,
                         cudaFuncAttributeMaxDynamicSharedMemorySize, SM128);

    cudaMemsetAsync(out, 0, (size_t)VOX * 128 * sizeof(float), 0);

    const int NPREP = 2 * (64 * 64 * 9) + 2 * (128 * 64 * 9);
    prep<<<(NPREP + 255) / 256, 256>>>(W1a, W1b, W2a, W2b);
    pass0<<<VOX / 256, 256>>>(x);

    const int NB = VOX / 64;  // worst-case all-active; blocks early-exit past g_count
    conv_gn<64, 0, true,  false><<<NB, 256, SM64>>>(p_xa, p_w1a, g1a, b1a, p_s1, nullptr, nullptr);
    conv_gn<128, 1, false, false><<<NB, 256, SM128>>>(p_s1, p_w1b, g1b, b1b, p_sc, nullptr, nullptr);
    conv_gn<64, 2, true,  false><<<NB, 256, SM64>>>(p_xa, p_w2a, g2a, b2a, p_r1, nullptr, nullptr);
    conv_gn<128, 0, false, true><<<NB, 256, SM128>>>(p_r1, p_w2b, g2b, b2b, nullptr, p_sc, out);
}